// round 7
// baseline (speedup 1.0000x reference)
#include <cuda_runtime.h>

// FullSpikeFunction: LIF recurrence with adaptive threshold + refractory.
// x[B=16, T=4096, N=1024] fp32 -> z[B, T, N] fp32.
//
// Numerics contract (deduced across rounds):
//  R2: z treated as exact {0,1}          -> rel_err 1.16e-2
//  R6: exact UNFUSED HLO rounding        -> rel_err 7.8e-3
//  => reference XLA contracts mul+add to FMA (xla_allow_excess_precision
//     default). LLVM DAG combiner fuses the LHS fmul of each fadd/fsub,
//     one-use only:
//    m  = fl(0.1f*x)
//    s  = fmaf(0.9f, u, m)            // fadd(fmul(al,u), m) -> fma
//    u  = fmaf(-z_prev, rg, s)        // fsub(s, fmul(z,rg)) -> fma(-z,rg,s)
//    v  = fl(u - b)
//    d  = fl(v - 1)
//    zb = fl(fl(-0.5f*fl(d*d)) * 0.3f)      (masked |v|<1; v>0 branch)
//    z  = fire ? fl(fl(1 - zb) + zb) : 0    // zb has TWO uses -> NOT fused;
//                                           // z = 1 +/- 1ulp, not exactly 1
//    q  = max(0, q-1) + (z >= 1.0f ? 5 : 0) // f32->s32 truncation semantics
//    b  = fmaf(0.95f, b, fl(fl(0.05f*z)*tg))
//
// 16384 independent lanes (hard parallelism cap), one per thread, coalesced
// across n. Double-buffered time unroll keeps 16 loads/thread in flight.

namespace {
constexpr int kB = 16;
constexpr int kT = 4096;
constexpr int kN = 1024;
constexpr int kU = 16;            // time unroll / prefetch group
constexpr int kThreads = 64;
constexpr int kBlocks = (kB * kN + kThreads - 1) / kThreads;   // 256
}  // namespace

__global__ __launch_bounds__(kThreads, 2)
void full_spike_kernel(const float* __restrict__ x,
                       const float* __restrict__ reset_gamma,
                       const float* __restrict__ thr_gamma,
                       const float* __restrict__ u0,
                       const float* __restrict__ b0,
                       float* __restrict__ out)
{
    const int idx = blockIdx.x * kThreads + threadIdx.x;   // 0 .. B*N-1
    if (idx >= kB * kN) return;
    const int n = idx & (kN - 1);
    const int b = idx >> 10;                                // idx / kN

    const size_t base = (size_t)b * kT * kN + n;
    const float* xp = x + base;
    float* zp = out + base;

    float u  = u0[n];
    float bb = b0[n];
    const float rg = reset_gamma[n];
    const float tg = thr_gamma[n];
    int   q  = 0;
    float zprev = 0.0f;   // last_z (carry), feeds fma(-z, rg, s)

    float xbuf[2][kU];

    // prime group 0
    #pragma unroll
    for (int i = 0; i < kU; ++i)
        xbuf[0][i] = __ldcs(xp + (size_t)i * kN);

    const int ngroups = kT / kU;
    for (int g = 0; g < ngroups; ++g) {
        const int cur = g & 1;

        // issue next group's loads first (independent of the recurrence)
        if (g + 1 < ngroups) {
            const float* xn = xp + (size_t)(g + 1) * kU * kN;
            #pragma unroll
            for (int i = 0; i < kU; ++i)
                xbuf[cur ^ 1][i] = __ldcs(xn + (size_t)i * kN);
        }

        float* zg = zp + (size_t)g * kU * kN;
        #pragma unroll
        for (int i = 0; i < kU; ++i) {
            const float xt = xbuf[cur][i];

            // u update with XLA's FMA contraction pattern.
            const float m = __fmul_rn(0.1f, xt);
            const float s = __fmaf_rn(0.9f, u, m);
            u = __fmaf_rn(-zprev, rg, s);
            const float v = __fadd_rn(u, -bb);

            // surrogate-spike forward value (UNFUSED: zb is two-use):
            // zb = where(|v|<1, -0.5*(v-1)^2, .) * 0.3 ; z = (1 - zb) + zb
            const float d = __fadd_rn(v, -1.0f);
            float zb = __fmul_rn(-0.5f, __fmul_rn(d, d));
            zb = (fabsf(v) < 1.0f) ? zb : 0.0f;
            zb = __fmul_rn(zb, 0.3f);
            const float zspike = __fadd_rn(__fadd_rn(1.0f, -zb), zb);

            const bool fire = (v > 0.0f) && (q == 0);
            const float z = fire ? zspike : 0.0f;   // non-fire exactly 0

            // q = max(0, q-1) + 5*trunc(z); z in {0} U [1-2ulp, 1+2ulp]
            q = (q > 0) ? (q - 1) : 0;
            q += (z >= 1.0f) ? 5 : 0;

            // b update: LHS mul fused, RHS mul chain unfused.
            bb = __fmaf_rn(0.95f, bb,
                           __fmul_rn(__fmul_rn(0.05f, z), tg));

            zprev = z;

            __stcs(zg + (size_t)i * kN, z);
        }
    }
}

extern "C" void kernel_launch(void* const* d_in, const int* in_sizes, int n_in,
                              void* d_out, int out_size)
{
    const float* x           = (const float*)d_in[0];
    const float* reset_gamma = (const float*)d_in[1];
    const float* thr_gamma   = (const float*)d_in[2];
    const float* u0          = (const float*)d_in[3];
    const float* b0          = (const float*)d_in[4];
    float* out = (float*)d_out;

    full_spike_kernel<<<kBlocks, kThreads>>>(x, reset_gamma, thr_gamma, u0, b0, out);
}

// round 8
// speedup vs baseline: 1.2618x; 1.2618x over previous
#include <cuda_runtime.h>

// FullSpikeFunction: LIF recurrence with adaptive threshold + refractory.
// x[B=16, T=4096, N=1024] fp32 -> z[B, T, N] fp32.
//
// Numerics contract (validated rel_err==0.0 in R7): XLA fuses the LHS fmul of
// each fadd/fsub (one-use only), the two-use spike crumb stays unfused:
//   m  = fl(0.1f*x); s = fmaf(0.9f,u,m); u = fmaf(-z_prev,rg,s)
//   v  = fl(u-b); d = fl(v-1)
//   zb = fl(fl(-0.5f*fl(d*d)))*0.3f   (masked |v|<1)
//   z  = fire ? fl(fl(1-zb)+zb) : 0   (fire = v>0 && q==0; z = 1 +/- ulp)
//   q  = max(0,q-1) + (z>=1.0f ? 5:0) (f32->s32 trunc semantics)
//   b  = fmaf(0.95f,b, fl(fl(0.05f*z)*tg))
//
// R7 perf post-mortem: 426us, latency-bound (~198 cyc/iter vs ~65 chain).
// Root cause: xbuf[2][kU] indexed by runtime (g&1) -> local memory demotion
// (LDL/STL on every consume/prefetch). This version:
//   - statically named double buffers + outer loop unrolled x2 (compile-time
//     buffer selection, pure register residency)
//   - 2 lanes/thread via float2: halves ld/st/addr work per lane-step and
//     interleaves two independent chains to hide predicate/FMA latency
//   - 256 blocks x 32 threads: all 148 SMs busy, <=1 warp/SMSP

namespace {
constexpr int kB = 16;
constexpr int kT = 4096;
constexpr int kN = 1024;
constexpr int kN2 = kN / 2;       // float2 columns
constexpr int kU = 16;            // time steps per prefetch group
constexpr int kThreads = 32;
constexpr int kLanes2 = kB * kN2;                    // 8192 float2 lanes
constexpr int kBlocks = kLanes2 / kThreads;          // 256
}  // namespace

// One time-step for one scalar lane, exact reference rounding.
__device__ __forceinline__ float lif_step(float xt, float& u, float& bb,
                                          int& q, float& zprev,
                                          float rg, float tg)
{
    const float m = __fmul_rn(0.1f, xt);
    const float s = __fmaf_rn(0.9f, u, m);
    u = __fmaf_rn(-zprev, rg, s);
    const float v = __fadd_rn(u, -bb);

    const float d = __fadd_rn(v, -1.0f);
    float zb = __fmul_rn(-0.5f, __fmul_rn(d, d));
    zb = (fabsf(v) < 1.0f) ? zb : 0.0f;
    zb = __fmul_rn(zb, 0.3f);
    const float zspike = __fadd_rn(__fadd_rn(1.0f, -zb), zb);

    const bool fire = (v > 0.0f) && (q == 0);
    const float z = fire ? zspike : 0.0f;

    q = (q > 0) ? (q - 1) : 0;
    q += (z >= 1.0f) ? 5 : 0;

    bb = __fmaf_rn(0.95f, bb, __fmul_rn(__fmul_rn(0.05f, z), tg));
    zprev = z;
    return z;
}

__global__ __launch_bounds__(kThreads)
void full_spike_kernel(const float2* __restrict__ x,
                       const float* __restrict__ reset_gamma,
                       const float* __restrict__ thr_gamma,
                       const float* __restrict__ u0,
                       const float* __restrict__ b0,
                       float2* __restrict__ out)
{
    const int idx = blockIdx.x * kThreads + threadIdx.x;   // 0 .. kLanes2-1
    if (idx >= kLanes2) return;
    const int n2 = idx & (kN2 - 1);          // float2 column
    const int b  = idx >> 9;                 // idx / kN2
    const int n  = n2 * 2;

    const size_t base = (size_t)b * kT * kN2 + n2;   // in float2 units
    const float2* xp = x + base;
    float2* zp = out + base;

    float ux = u0[n],     uy = u0[n + 1];
    float bx = b0[n],     by = b0[n + 1];
    const float rgx = reset_gamma[n], rgy = reset_gamma[n + 1];
    const float tgx = thr_gamma[n],   tgy = thr_gamma[n + 1];
    int   qx = 0,  qy = 0;
    float zpx = 0.0f, zpy = 0.0f;

    float2 bufA[kU], bufB[kU];

    // prime bufA with group 0
    #pragma unroll
    for (int i = 0; i < kU; ++i)
        bufA[i] = __ldcs(xp + (size_t)i * kN2);

    const int ngroups = kT / kU;   // 256 (even)
    for (int g = 0; g < ngroups; g += 2) {
        // ---- half A: prefetch group g+1 into bufB, consume bufA ----
        {
            const float2* xn = xp + (size_t)(g + 1) * kU * kN2;
            #pragma unroll
            for (int i = 0; i < kU; ++i)
                bufB[i] = __ldcs(xn + (size_t)i * kN2);
        }
        {
            float2* zg = zp + (size_t)g * kU * kN2;
            #pragma unroll
            for (int i = 0; i < kU; ++i) {
                const float2 xt = bufA[i];
                float2 z;
                z.x = lif_step(xt.x, ux, bx, qx, zpx, rgx, tgx);
                z.y = lif_step(xt.y, uy, by, qy, zpy, rgy, tgy);
                __stcs(zg + (size_t)i * kN2, z);
            }
        }

        // ---- half B: prefetch group g+2 into bufA, consume bufB ----
        if (g + 2 < ngroups) {
            const float2* xn = xp + (size_t)(g + 2) * kU * kN2;
            #pragma unroll
            for (int i = 0; i < kU; ++i)
                bufA[i] = __ldcs(xn + (size_t)i * kN2);
        }
        {
            float2* zg = zp + (size_t)(g + 1) * kU * kN2;
            #pragma unroll
            for (int i = 0; i < kU; ++i) {
                const float2 xt = bufB[i];
                float2 z;
                z.x = lif_step(xt.x, ux, bx, qx, zpx, rgx, tgx);
                z.y = lif_step(xt.y, uy, by, qy, zpy, rgy, tgy);
                __stcs(zg + (size_t)i * kN2, z);
            }
        }
    }
}

extern "C" void kernel_launch(void* const* d_in, const int* in_sizes, int n_in,
                              void* d_out, int out_size)
{
    const float2* x          = (const float2*)d_in[0];
    const float* reset_gamma = (const float*)d_in[1];
    const float* thr_gamma   = (const float*)d_in[2];
    const float* u0          = (const float*)d_in[3];
    const float* b0          = (const float*)d_in[4];
    float2* out = (float2*)d_out;

    full_spike_kernel<<<kBlocks, kThreads>>>(x, reset_gamma, thr_gamma, u0, b0, out);
}

// round 10
// speedup vs baseline: 1.5365x; 1.2177x over previous
#include <cuda_runtime.h>

// FullSpikeFunction: LIF recurrence with adaptive threshold + refractory.
// x[B=16, T=4096, N=1024] fp32 -> z[B, T, N] fp32.
//
// (Resubmission: R9 bench died to container infra flake before compile/run.
// The R8->R9 theory is untested; no evidence-driven change to make.)
//
// Numerics contract (validated rel_err==0.0 in R7/R8): XLA fuses the LHS fmul
// of each fadd/fsub (one-use only); the two-use spike crumb stays unfused:
//   m  = fl(0.1f*x); s = fmaf(0.9f,u,m); u = fmaf(-z_prev,rg,s)
//   v  = fl(u-b); d = fl(v-1)
//   crumb: zb = fl(fl(-0.5f*fl(d*d))*0.3f); zsp = fl(fl(1-zb)+zb)
//   z1 = (v<1) ? zsp : 1.0f        // |v|>=1 & fire => zb masked to 0 => z=1.0
//   z  = (v>0 && q==0) ? z1 : 0.0f // z = 1 +/- ulp when firing, never exact
//   q  = max(0,q-1) + (z>=1.0f ? 5 : 0)   // f32->s32 trunc semantics
//   b  = fmaf(0.95f,b, fl(fl(0.05f*z)*tg))
//
// R8 post-mortem: 82 cyc/lane-step == single-warp SMSP issue bound
// (~45 slots x rt2 pipes + STG.64), NOT chain- or DRAM-bound. Fix: 1 lane
// per thread -> 512 warps ~= one per SMSP chip-wide, halving per-warp issue
// work per step. Static double-buffered registers (no dynamic indexing ->
// no local-memory demotion), outer loop unrolled x2.

namespace {
constexpr int kB = 16;
constexpr int kT = 4096;
constexpr int kN = 1024;
constexpr int kU = 16;            // time steps per prefetch group
constexpr int kThreads = 64;
constexpr int kLanes = kB * kN;                      // 16384
constexpr int kBlocks = kLanes / kThreads;           // 256
}  // namespace

// One time-step, exact reference rounding.
__device__ __forceinline__ float lif_step(float xt, float& u, float& bb,
                                          int& q, float& zprev,
                                          float rg, float tg)
{
    const float m = __fmul_rn(0.1f, xt);
    const float s = __fmaf_rn(0.9f, u, m);
    u = __fmaf_rn(-zprev, rg, s);
    const float v = __fadd_rn(u, -bb);

    // unmasked crumb chain
    const float d  = __fadd_rn(v, -1.0f);
    const float zb = __fmul_rn(__fmul_rn(-0.5f, __fmul_rn(d, d)), 0.3f);
    const float zsp = __fadd_rn(__fadd_rn(1.0f, -zb), zb);

    // select topology: |v|>=1 (with v>0) => z = 1.0 exactly
    const float z1 = (v < 1.0f) ? zsp : 1.0f;
    const bool fire = (v > 0.0f) && (q == 0);
    const float z = fire ? z1 : 0.0f;

    q = max(q - 1, 0);
    q += (z >= 1.0f) ? 5 : 0;

    bb = __fmaf_rn(0.95f, bb, __fmul_rn(__fmul_rn(0.05f, z), tg));
    zprev = z;
    return z;
}

__global__ __launch_bounds__(kThreads)
void full_spike_kernel(const float* __restrict__ x,
                       const float* __restrict__ reset_gamma,
                       const float* __restrict__ thr_gamma,
                       const float* __restrict__ u0,
                       const float* __restrict__ b0,
                       float* __restrict__ out)
{
    const int idx = blockIdx.x * kThreads + threadIdx.x;   // 0 .. kLanes-1
    if (idx >= kLanes) return;
    const int n = idx & (kN - 1);
    const int b = idx >> 10;

    const size_t base = (size_t)b * kT * kN + n;
    const float* xp = x + base;
    float* zp = out + base;

    float u  = u0[n];
    float bb = b0[n];
    const float rg = reset_gamma[n];
    const float tg = thr_gamma[n];
    int   q = 0;
    float zprev = 0.0f;

    float bufA[kU], bufB[kU];

    // prime bufA with group 0
    #pragma unroll
    for (int i = 0; i < kU; ++i)
        bufA[i] = __ldcs(xp + (size_t)i * kN);

    const int ngroups = kT / kU;   // 256 (even)
    for (int g = 0; g < ngroups; g += 2) {
        // half A: prefetch group g+1 into bufB, consume bufA
        {
            const float* xn = xp + (size_t)(g + 1) * kU * kN;
            #pragma unroll
            for (int i = 0; i < kU; ++i)
                bufB[i] = __ldcs(xn + (size_t)i * kN);
        }
        {
            float* zg = zp + (size_t)g * kU * kN;
            #pragma unroll
            for (int i = 0; i < kU; ++i)
                __stcs(zg + (size_t)i * kN,
                       lif_step(bufA[i], u, bb, q, zprev, rg, tg));
        }

        // half B: prefetch group g+2 into bufA, consume bufB
        if (g + 2 < ngroups) {
            const float* xn = xp + (size_t)(g + 2) * kU * kN;
            #pragma unroll
            for (int i = 0; i < kU; ++i)
                bufA[i] = __ldcs(xn + (size_t)i * kN);
        }
        {
            float* zg = zp + (size_t)(g + 1) * kU * kN;
            #pragma unroll
            for (int i = 0; i < kU; ++i)
                __stcs(zg + (size_t)i * kN,
                       lif_step(bufB[i], u, bb, q, zprev, rg, tg));
        }
    }
}

extern "C" void kernel_launch(void* const* d_in, const int* in_sizes, int n_in,
                              void* d_out, int out_size)
{
    const float* x           = (const float*)d_in[0];
    const float* reset_gamma = (const float*)d_in[1];
    const float* thr_gamma   = (const float*)d_in[2];
    const float* u0          = (const float*)d_in[3];
    const float* b0          = (const float*)d_in[4];
    float* out = (float*)d_out;

    full_spike_kernel<<<kBlocks, kThreads>>>(x, reset_gamma, thr_gamma, u0, b0, out);
}